// round 1
// baseline (speedup 1.0000x reference)
#include <cuda_runtime.h>
#include <cuda_bf16.h>
#include <math.h>

// Problem constants
#define BB 4
#define TT 8192
#define DDIM 512
#define HH 8
#define DH 64
#define MM (BB*TT)     // 32768 rows
#define NCHUNK 8       // T-chunks for context reduction

// Scratch (device globals: no cudaMalloc allowed)
__device__ float g_qh[(size_t)MM*DDIM];   // elu(q@Wq^T+bq)+1
__device__ float g_kh[(size_t)MM*DDIM];   // elu(k@Wk^T+bk)+1
__device__ float g_vh[(size_t)MM*DDIM];   // v@Wv^T+bv
__device__ float g_att[(size_t)MM*DDIM];  // normalized attention output
__device__ float g_ctx[BB*HH*DH*DH];      // per-(b,h) K^T V   [64x64]
__device__ float g_ksum[BB*HH*DH];        // per-(b,h) sum_t k [64]

// ---------------------------------------------------------------------------
// GEMM: Y[m,n] = sum_k X[m,k] * W[n,k] + bias[n]   (x @ W^T + b)
// M=32768, N=512, K=512.  128x128 block tile, BK=8, 8x8 per-thread microtile.
// act=1 applies elu(x)+1 (x>0 ? x+1 : exp(x)).
// xsel: 0 -> Xext, 1 -> g_att.  ysel: 0 -> Yext, 1/2/3 -> g_qh/g_kh/g_vh.
// ---------------------------------------------------------------------------
__global__ __launch_bounds__(256)
void gemm_kernel(const float* __restrict__ Xext, int xsel,
                 const float* __restrict__ W,
                 const float* __restrict__ bias,
                 float* __restrict__ Yext, int ysel, int act)
{
    const float* X = (xsel == 1) ? g_att : Xext;
    float* Y = Yext;
    if      (ysel == 1) Y = g_qh;
    else if (ysel == 2) Y = g_kh;
    else if (ysel == 3) Y = g_vh;

    __shared__ float As[8][128];
    __shared__ float Bs[8][128];

    const int tid = threadIdx.x;
    const int m0 = blockIdx.y * 128;
    const int n0 = blockIdx.x * 128;
    const int lr = tid >> 1;          // 0..127
    const int lc = (tid & 1) << 2;    // 0 or 4
    const float* Ap = X + (size_t)(m0 + lr) * DDIM + lc;
    const float* Bp = W + (size_t)(n0 + lr) * DDIM + lc;
    const int tx = tid & 15;
    const int ty = tid >> 4;

    float acc[8][8];
#pragma unroll
    for (int i = 0; i < 8; i++)
#pragma unroll
        for (int j = 0; j < 8; j++) acc[i][j] = 0.f;

    for (int k0 = 0; k0 < DDIM; k0 += 8) {
        float4 a4 = *(const float4*)(Ap + k0);
        float4 b4 = *(const float4*)(Bp + k0);
        As[lc+0][lr] = a4.x; As[lc+1][lr] = a4.y; As[lc+2][lr] = a4.z; As[lc+3][lr] = a4.w;
        Bs[lc+0][lr] = b4.x; Bs[lc+1][lr] = b4.y; Bs[lc+2][lr] = b4.z; Bs[lc+3][lr] = b4.w;
        __syncthreads();
#pragma unroll
        for (int kk = 0; kk < 8; kk++) {
            float4 a0 = *(const float4*)&As[kk][ty*8];
            float4 a1 = *(const float4*)&As[kk][ty*8+4];
            float4 b0 = *(const float4*)&Bs[kk][tx*8];
            float4 b1 = *(const float4*)&Bs[kk][tx*8+4];
            float ar[8] = {a0.x,a0.y,a0.z,a0.w,a1.x,a1.y,a1.z,a1.w};
            float br[8] = {b0.x,b0.y,b0.z,b0.w,b1.x,b1.y,b1.z,b1.w};
#pragma unroll
            for (int i = 0; i < 8; i++)
#pragma unroll
                for (int j = 0; j < 8; j++)
                    acc[i][j] += ar[i] * br[j];
        }
        __syncthreads();
    }

#pragma unroll
    for (int i = 0; i < 8; i++) {
        const int m = m0 + ty*8 + i;
#pragma unroll
        for (int j4 = 0; j4 < 8; j4 += 4) {
            const int n = n0 + tx*8 + j4;
            float4 o;
            o.x = acc[i][j4+0] + bias[n+0];
            o.y = acc[i][j4+1] + bias[n+1];
            o.z = acc[i][j4+2] + bias[n+2];
            o.w = acc[i][j4+3] + bias[n+3];
            if (act) {
                o.x = (o.x > 0.f) ? o.x + 1.f : expf(o.x);
                o.y = (o.y > 0.f) ? o.y + 1.f : expf(o.y);
                o.z = (o.z > 0.f) ? o.z + 1.f : expf(o.z);
                o.w = (o.w > 0.f) ? o.w + 1.f : expf(o.w);
            }
            *(float4*)(Y + (size_t)m * DDIM + n) = o;
        }
    }
}

// ---------------------------------------------------------------------------
// Zero the accumulators for ctx/ksum before the atomic reduction.
// ---------------------------------------------------------------------------
__global__ void zero_kernel()
{
    int i = blockIdx.x * blockDim.x + threadIdx.x;
    if (i < BB*HH*DH*DH) g_ctx[i]  = 0.f;
    if (i < BB*HH*DH)    g_ksum[i] = 0.f;
}

// ---------------------------------------------------------------------------
// Context reduction: ctx[b,h,c,d] = sum_t kh[b,t,h,c]*vh[b,t,h,d]
//                    ksum[b,h,c]  = sum_t kh[b,t,h,c]
// grid = (B*H, NCHUNK), 256 threads. Each block: 1024 t's in 32-row smem tiles,
// 4x4 microtile per thread over the 64x64 output; atomicAdd partials.
// ---------------------------------------------------------------------------
__global__ __launch_bounds__(256)
void ctx_kernel()
{
    const int bh = blockIdx.x;            // 0..31
    const int chunk = blockIdx.y;         // 0..NCHUNK-1
    const int b = bh >> 3, h = bh & 7;

    __shared__ float ks[32][64];
    __shared__ float vs[32][64];

    const int tid = threadIdx.x;
    const int cb = tid >> 4;              // 0..15  -> c block
    const int db = tid & 15;              // 0..15  -> d block

    float acc[4][4];
#pragma unroll
    for (int i = 0; i < 4; i++)
#pragma unroll
        for (int j = 0; j < 4; j++) acc[i][j] = 0.f;
    float ksacc = 0.f;

    const int tbase = b*TT + chunk * (TT/NCHUNK);

    for (int tt = 0; tt < TT/NCHUNK; tt += 32) {
        // load 32x64 tiles of kh and vh (512 float4 each; 2 per thread)
#pragma unroll
        for (int qq = 0; qq < 2; qq++) {
            const int fi = qq*256 + tid;
            const int r  = fi >> 4;
            const int c4 = fi & 15;
            const size_t g = (size_t)(tbase + tt + r) * DDIM + h*DH + c4*4;
            *(float4*)&ks[r][c4*4] = *(const float4*)(g_kh + g);
            *(float4*)&vs[r][c4*4] = *(const float4*)(g_vh + g);
        }
        __syncthreads();

        if (tid < 64) {
#pragma unroll
            for (int t = 0; t < 32; t++) ksacc += ks[t][tid];
        }

#pragma unroll 8
        for (int t = 0; t < 32; t++) {
            float4 av = *(const float4*)&ks[t][cb*4];
            float4 bv = *(const float4*)&vs[t][db*4];
            float ar[4] = {av.x, av.y, av.z, av.w};
            float br[4] = {bv.x, bv.y, bv.z, bv.w};
#pragma unroll
            for (int i = 0; i < 4; i++)
#pragma unroll
                for (int j = 0; j < 4; j++)
                    acc[i][j] += ar[i] * br[j];
        }
        __syncthreads();
    }

    float* cp = g_ctx + bh * DH * DH;
#pragma unroll
    for (int i = 0; i < 4; i++)
#pragma unroll
        for (int j = 0; j < 4; j++)
            atomicAdd(&cp[(cb*4+i)*DH + (db*4+j)], acc[i][j]);
    if (tid < 64) atomicAdd(&g_ksum[bh*DH + tid], ksacc);
}

// ---------------------------------------------------------------------------
// Apply: num[t,d] = sum_c qh[t,c]*ctx[c,d];  den[t] = sum_c qh[t,c]*ksum[c]
//        g_att[t,d] = num/den.
// grid = (B*H, T/64), 256 threads. ctx + 64 q-rows cached in smem.
// Each thread: 4 t-rows x 4 d-cols (float4 ctx loads -> 4 FMA per 2 LDS).
// ---------------------------------------------------------------------------
__global__ __launch_bounds__(256)
void apply_kernel()
{
    const int bh = blockIdx.x;            // 0..31
    const int tile = blockIdx.y;          // 0..127 (64 t's each)
    const int b = bh >> 3, h = bh & 7;

    __shared__ float ctxs[64][68];        // pad 68: f4-aligned rows, fewer conflicts
    __shared__ float qsm[64][68];
    __shared__ float dsm[64];

    const int tid = threadIdx.x;
    const int t0 = tile * 64;
    const float* cp = g_ctx + bh * 4096;

    // load ctx (64x64) and qh rows (64x64): 256 float4 per pass, 4 passes each
#pragma unroll
    for (int qq = 0; qq < 4; qq++) {
        const int fi = qq*256 + tid;      // 0..1023
        const int r  = fi >> 4;
        const int c4 = fi & 15;
        *(float4*)&ctxs[r][c4*4] = *(const float4*)(cp + r*64 + c4*4);
        const size_t g = (size_t)(b*TT + t0 + r) * DDIM + h*DH + c4*4;
        *(float4*)&qsm[r][c4*4] = *(const float4*)(g_qh + g);
    }
    __syncthreads();

    if (tid < 64) {
        const float* kp = g_ksum + bh * DH;
        float dn = 0.f;
#pragma unroll
        for (int c = 0; c < 64; c++) dn += qsm[tid][c] * kp[c];
        dsm[tid] = dn;
    }
    __syncthreads();

    const int tsub = tid >> 4;            // 0..15
    const int dq   = (tid & 15) * 4;      // 0,4,...,60
#pragma unroll
    for (int ts = 0; ts < 4; ts++) {
        const int t = ts*16 + tsub;
        float4 acc = {0.f, 0.f, 0.f, 0.f};
#pragma unroll
        for (int c = 0; c < 64; c++) {
            const float qv = qsm[t][c];
            const float4 cv = *(const float4*)&ctxs[c][dq];
            acc.x += qv * cv.x;
            acc.y += qv * cv.y;
            acc.z += qv * cv.z;
            acc.w += qv * cv.w;
        }
        const float inv = 1.f / dsm[t];
        float4 o = {acc.x*inv, acc.y*inv, acc.z*inv, acc.w*inv};
        const size_t g = (size_t)(b*TT + t0 + t) * DDIM + h*DH + dq;
        *(float4*)(g_att + g) = o;
    }
}

// ---------------------------------------------------------------------------
extern "C" void kernel_launch(void* const* d_in, const int* in_sizes, int n_in,
                              void* d_out, int out_size)
{
    const float* q  = (const float*)d_in[0];
    const float* k  = (const float*)d_in[1];
    const float* v  = (const float*)d_in[2];
    const float* Wq = (const float*)d_in[3];
    const float* bq = (const float*)d_in[4];
    const float* Wk = (const float*)d_in[5];
    const float* bk = (const float*)d_in[6];
    const float* Wv = (const float*)d_in[7];
    const float* bv = (const float*)d_in[8];
    const float* Wo = (const float*)d_in[9];
    const float* bo = (const float*)d_in[10];
    float* out = (float*)d_out;

    dim3 gg(DDIM/128, MM/128);   // (4, 256)

    gemm_kernel<<<gg, 256>>>(q, 0, Wq, bq, nullptr, 1, 1);   // qh = elu(qWq^T+bq)+1
    gemm_kernel<<<gg, 256>>>(k, 0, Wk, bk, nullptr, 2, 1);   // kh
    gemm_kernel<<<gg, 256>>>(v, 0, Wv, bv, nullptr, 3, 0);   // vh
    zero_kernel<<<(BB*HH*DH*DH + 255)/256, 256>>>();
    ctx_kernel<<<dim3(BB*HH, NCHUNK), 256>>>();
    apply_kernel<<<dim3(BB*HH, TT/64), 256>>>();
    gemm_kernel<<<gg, 256>>>(nullptr, 1, Wo, bo, out, 0, 0); // out = att@Wo^T+bo
}

// round 3
// speedup vs baseline: 2.2527x; 2.2527x over previous
#include <cuda_runtime.h>
#include <cuda_bf16.h>
#include <math.h>
#include <stdint.h>

// Problem constants
#define BB 4
#define TT 8192
#define DDIM 512
#define HH 8
#define DH 64
#define MM (BB*TT)     // 32768 rows
#define NCHUNK 8       // T-chunks for context reduction

// GEMM tiling (mma.sync path)
#define KC 32                       // bf16 K elements per chunk
#define NCHUNKS (DDIM/KC)           // 16
#define RSTRIDE 80                  // padded smem row stride in bytes (64B data + 16B pad)
#define TILEB (128*RSTRIDE)         // 10240 bytes per tile
#define STAGEB (4*TILEB)            // Ahi,Alo,Bhi,Blo = 40960
#define GEMM_SMEM (2*STAGEB)        // 81920

// Scratch (device globals: no cudaMalloc allowed)
__device__ float g_qh[(size_t)MM*DDIM];
__device__ float g_kh[(size_t)MM*DDIM];
__device__ float g_vh[(size_t)MM*DDIM];
__device__ float g_att[(size_t)MM*DDIM];
__device__ float g_ctx[BB*HH*DH*DH];
__device__ float g_ksum[BB*HH*DH];

// ---------------------------------------------------------------------------
// helpers
// ---------------------------------------------------------------------------
__device__ __forceinline__ uint32_t smem_u32(const void* p) {
    uint32_t a;
    asm("{ .reg .u64 t; cvta.to.shared.u64 t, %1; cvt.u32.u64 %0, t; }" : "=r"(a) : "l"(p));
    return a;
}
__device__ __forceinline__ void ldsm4(uint32_t* r, uint32_t addr) {
    asm volatile("ldmatrix.sync.aligned.m8n8.x4.shared.b16 {%0,%1,%2,%3}, [%4];"
                 : "=r"(r[0]), "=r"(r[1]), "=r"(r[2]), "=r"(r[3]) : "r"(addr));
}
__device__ __forceinline__ void mma_bf16(float* c, const uint32_t* a, const uint32_t* b) {
    asm volatile("mma.sync.aligned.m16n8k16.row.col.f32.bf16.bf16.f32 "
                 "{%0,%1,%2,%3}, {%4,%5,%6,%7}, {%8,%9}, {%0,%1,%2,%3};"
                 : "+f"(c[0]), "+f"(c[1]), "+f"(c[2]), "+f"(c[3])
                 : "r"(a[0]), "r"(a[1]), "r"(a[2]), "r"(a[3]), "r"(b[0]), "r"(b[1]));
}
// packs: high half = hi_f, low half = lo_f (memory order: lo first)
__device__ __forceinline__ uint32_t cvt_bf16x2(float hi_f, float lo_f) {
    uint32_t r;
    asm("cvt.rn.bf16x2.f32 %0, %1, %2;" : "=r"(r) : "f"(hi_f), "f"(lo_f));
    return r;
}
__device__ __forceinline__ void cvt_hl(float4 v, uint2& hi, uint2& lo) {
    uint32_t h01 = cvt_bf16x2(v.y, v.x);
    uint32_t h23 = cvt_bf16x2(v.w, v.z);
    float fx = __uint_as_float(h01 << 16);
    float fy = __uint_as_float(h01 & 0xFFFF0000u);
    float fz = __uint_as_float(h23 << 16);
    float fw = __uint_as_float(h23 & 0xFFFF0000u);
    hi.x = h01; hi.y = h23;
    lo.x = cvt_bf16x2(v.y - fy, v.x - fx);
    lo.y = cvt_bf16x2(v.w - fw, v.z - fz);
}

// ---------------------------------------------------------------------------
// GEMM: Y[m,n] = sum_k X[m,k]*W[n,k] + bias[n]  (optionally elu(x)+1)
// 128x128 CTA tile, 8 warps (2m x 4n), warp tile 64x32, hi/lo bf16 3-MMA split.
// ---------------------------------------------------------------------------
__device__ __forceinline__ void ldg_chunk(const float* __restrict__ X, const float* __restrict__ W,
                                          int m0, int n0, int k0, int tid,
                                          float4* ra, float4* rb) {
#pragma unroll
    for (int q = 0; q < 4; q++) {
        int f = q * 256 + tid;          // 0..1023
        int r = f >> 3;                 // 0..127
        int c = (f & 7) * 4;            // float col 0..28
        ra[q] = *(const float4*)(X + (size_t)(m0 + r) * DDIM + k0 + c);
        rb[q] = *(const float4*)(W + (size_t)(n0 + r) * DDIM + k0 + c);
    }
}
__device__ __forceinline__ void sts_chunk(char* base, int tid, const float4* ra, const float4* rb) {
#pragma unroll
    for (int q = 0; q < 4; q++) {
        int f = q * 256 + tid;
        int r = f >> 3;
        int c8 = (f & 7) * 8;           // byte offset within 64B row data
        uint2 h, l;
        cvt_hl(ra[q], h, l);
        *(uint2*)(base + r * RSTRIDE + c8) = h;
        *(uint2*)(base + TILEB + r * RSTRIDE + c8) = l;
        cvt_hl(rb[q], h, l);
        *(uint2*)(base + 2 * TILEB + r * RSTRIDE + c8) = h;
        *(uint2*)(base + 3 * TILEB + r * RSTRIDE + c8) = l;
    }
}

__global__ void __launch_bounds__(256)
gemm_mma(const float* __restrict__ Xext, int xsel,
         const float* __restrict__ W,
         const float* __restrict__ bias,
         float* __restrict__ Yext, int ysel, int act)
{
    extern __shared__ char smem[];
    const float* X = (xsel == 1) ? g_att : Xext;
    float* Y = Yext;
    if      (ysel == 1) Y = g_qh;
    else if (ysel == 2) Y = g_kh;
    else if (ysel == 3) Y = g_vh;

    const uint32_t sb = smem_u32(smem);
    const int tid = threadIdx.x;
    const int wid = tid >> 5, lane = tid & 31;
    const int wm = wid >> 2, wn = wid & 3;      // 2 x 4 warp grid
    const int g = lane >> 2, tg = lane & 3;
    const int m0 = blockIdx.y * 128, n0 = blockIdx.x * 128;

    float acc[4][4][4];
#pragma unroll
    for (int i = 0; i < 4; i++)
#pragma unroll
        for (int j = 0; j < 4; j++)
#pragma unroll
            for (int r = 0; r < 4; r++) acc[i][j][r] = 0.f;

    // precomputed ldmatrix address offsets (within a tile, given stage base)
    const uint32_t a_row = (uint32_t)(wm * 64 + (lane & 15));
    const uint32_t a_off = a_row * RSTRIDE + (uint32_t)(lane >> 4) * 16;
    const uint32_t b_row = (uint32_t)(wn * 32 + ((lane >> 4) * 8) + (lane & 7));
    const uint32_t b_off = b_row * RSTRIDE + (uint32_t)((lane >> 3) & 1) * 16;

    float4 ra[4], rb[4];

    // prologue
    ldg_chunk(X, W, m0, n0, 0, tid, ra, rb);
    sts_chunk(smem, tid, ra, rb);
    ldg_chunk(X, W, m0, n0, KC, tid, ra, rb);
    __syncthreads();

    for (int kc = 0; kc < NCHUNKS; kc++) {
        const int cur = kc & 1;
        const uint32_t st = sb + cur * STAGEB;

#pragma unroll
        for (int ks = 0; ks < 2; ks++) {
            const uint32_t kb = (uint32_t)ks * 32;
            uint32_t ah[4][4], al[4][4];
#pragma unroll
            for (int mi = 0; mi < 4; mi++) {
                uint32_t ad = st + a_off + (uint32_t)(mi * 16) * RSTRIDE + kb;
                ldsm4(ah[mi], ad);
                ldsm4(al[mi], ad + TILEB);
            }
            uint32_t bh[4][2], bl[4][2];
#pragma unroll
            for (int np = 0; np < 2; np++) {
                uint32_t r4[4];
                uint32_t bd = st + 2 * TILEB + b_off + (uint32_t)(np * 16) * RSTRIDE + kb;
                ldsm4(r4, bd);
                bh[np*2][0] = r4[0]; bh[np*2][1] = r4[1];
                bh[np*2+1][0] = r4[2]; bh[np*2+1][1] = r4[3];
                ldsm4(r4, bd + TILEB);
                bl[np*2][0] = r4[0]; bl[np*2][1] = r4[1];
                bl[np*2+1][0] = r4[2]; bl[np*2+1][1] = r4[3];
            }
#pragma unroll
            for (int mi = 0; mi < 4; mi++)
#pragma unroll
                for (int ni = 0; ni < 4; ni++) {
                    mma_bf16(acc[mi][ni], ah[mi], bh[ni]);
                    mma_bf16(acc[mi][ni], ah[mi], bl[ni]);
                    mma_bf16(acc[mi][ni], al[mi], bh[ni]);
                }
        }

        if (kc < NCHUNKS - 1) {
            sts_chunk(smem + (1 - cur) * STAGEB, tid, ra, rb);
            if (kc < NCHUNKS - 2)
                ldg_chunk(X, W, m0, n0, (kc + 2) * KC, tid, ra, rb);
        }
        __syncthreads();
    }

    // epilogue: bias + optional elu+1, write float2 pairs
#pragma unroll
    for (int mi = 0; mi < 4; mi++) {
#pragma unroll
        for (int ni = 0; ni < 4; ni++) {
            const int col = n0 + wn * 32 + ni * 8 + tg * 2;
            const float b0 = bias[col], b1 = bias[col + 1];
#pragma unroll
            for (int half = 0; half < 2; half++) {
                const int row = m0 + wm * 64 + mi * 16 + g + half * 8;
                float2 o;
                o.x = acc[mi][ni][half * 2 + 0] + b0;
                o.y = acc[mi][ni][half * 2 + 1] + b1;
                if (act) {
                    o.x = (o.x > 0.f) ? o.x + 1.f : expf(o.x);
                    o.y = (o.y > 0.f) ? o.y + 1.f : expf(o.y);
                }
                *(float2*)(Y + (size_t)row * DDIM + col) = o;
            }
        }
    }
}

// ---------------------------------------------------------------------------
// Zero accumulators
// ---------------------------------------------------------------------------
__global__ void zero_kernel()
{
    int i = blockIdx.x * blockDim.x + threadIdx.x;
    if (i < BB*HH*DH*DH) g_ctx[i]  = 0.f;
    if (i < BB*HH*DH)    g_ksum[i] = 0.f;
}

// ---------------------------------------------------------------------------
// Context reduction: ctx[b,h,c,d] = sum_t kh*vh ; ksum[b,h,c] = sum_t kh
// ---------------------------------------------------------------------------
__global__ __launch_bounds__(256)
void ctx_kernel()
{
    const int bh = blockIdx.x;
    const int chunk = blockIdx.y;
    const int b = bh >> 3, h = bh & 7;

    __shared__ float ks[32][64];
    __shared__ float vs[32][64];

    const int tid = threadIdx.x;
    const int cb = tid >> 4;
    const int db = tid & 15;

    float acc[4][4];
#pragma unroll
    for (int i = 0; i < 4; i++)
#pragma unroll
        for (int j = 0; j < 4; j++) acc[i][j] = 0.f;
    float ksacc = 0.f;

    const int tbase = b*TT + chunk * (TT/NCHUNK);

    for (int tt = 0; tt < TT/NCHUNK; tt += 32) {
#pragma unroll
        for (int qq = 0; qq < 2; qq++) {
            const int fi = qq*256 + tid;
            const int r  = fi >> 4;
            const int c4 = fi & 15;
            const size_t gofs = (size_t)(tbase + tt + r) * DDIM + h*DH + c4*4;
            *(float4*)&ks[r][c4*4] = *(const float4*)(g_kh + gofs);
            *(float4*)&vs[r][c4*4] = *(const float4*)(g_vh + gofs);
        }
        __syncthreads();

        if (tid < 64) {
#pragma unroll
            for (int t = 0; t < 32; t++) ksacc += ks[t][tid];
        }

#pragma unroll 8
        for (int t = 0; t < 32; t++) {
            float4 av = *(const float4*)&ks[t][cb*4];
            float4 bv = *(const float4*)&vs[t][db*4];
            float ar[4] = {av.x, av.y, av.z, av.w};
            float br[4] = {bv.x, bv.y, bv.z, bv.w};
#pragma unroll
            for (int i = 0; i < 4; i++)
#pragma unroll
                for (int j = 0; j < 4; j++)
                    acc[i][j] += ar[i] * br[j];
        }
        __syncthreads();
    }

    float* cp = g_ctx + bh * DH * DH;
#pragma unroll
    for (int i = 0; i < 4; i++)
#pragma unroll
        for (int j = 0; j < 4; j++)
            atomicAdd(&cp[(cb*4+i)*DH + (db*4+j)], acc[i][j]);
    if (tid < 64) atomicAdd(&g_ksum[bh*DH + tid], ksacc);
}

// ---------------------------------------------------------------------------
// Apply: g_att = (qh @ ctx) / (qh @ ksum)
// ---------------------------------------------------------------------------
__global__ __launch_bounds__(256)
void apply_kernel()
{
    const int bh = blockIdx.x;
    const int tile = blockIdx.y;
    const int b = bh >> 3, h = bh & 7;

    __shared__ float ctxs[64][68];
    __shared__ float qsm[64][68];
    __shared__ float dsm[64];

    const int tid = threadIdx.x;
    const int t0 = tile * 64;
    const float* cp = g_ctx + bh * 4096;

#pragma unroll
    for (int qq = 0; qq < 4; qq++) {
        const int fi = qq*256 + tid;
        const int r  = fi >> 4;
        const int c4 = fi & 15;
        *(float4*)&ctxs[r][c4*4] = *(const float4*)(cp + r*64 + c4*4);
        const size_t gofs = (size_t)(b*TT + t0 + r) * DDIM + h*DH + c4*4;
        *(float4*)&qsm[r][c4*4] = *(const float4*)(g_qh + gofs);
    }
    __syncthreads();

    if (tid < 64) {
        const float* kp = g_ksum + bh * DH;
        float dn = 0.f;
#pragma unroll
        for (int c = 0; c < 64; c++) dn += qsm[tid][c] * kp[c];
        dsm[tid] = dn;
    }
    __syncthreads();

    const int tsub = tid >> 4;
    const int dq   = (tid & 15) * 4;
#pragma unroll
    for (int ts = 0; ts < 4; ts++) {
        const int t = ts*16 + tsub;
        float4 acc = {0.f, 0.f, 0.f, 0.f};
#pragma unroll
        for (int c = 0; c < 64; c++) {
            const float qv = qsm[t][c];
            const float4 cv = *(const float4*)&ctxs[c][dq];
            acc.x += qv * cv.x;
            acc.y += qv * cv.y;
            acc.z += qv * cv.z;
            acc.w += qv * cv.w;
        }
        const float inv = 1.f / dsm[t];
        float4 o = {acc.x*inv, acc.y*inv, acc.z*inv, acc.w*inv};
        const size_t gofs = (size_t)(b*TT + t0 + t) * DDIM + h*DH + dq;
        *(float4*)(g_att + gofs) = o;
    }
}

// ---------------------------------------------------------------------------
extern "C" void kernel_launch(void* const* d_in, const int* in_sizes, int n_in,
                              void* d_out, int out_size)
{
    const float* q  = (const float*)d_in[0];
    const float* k  = (const float*)d_in[1];
    const float* v  = (const float*)d_in[2];
    const float* Wq = (const float*)d_in[3];
    const float* bq = (const float*)d_in[4];
    const float* Wk = (const float*)d_in[5];
    const float* bk = (const float*)d_in[6];
    const float* Wv = (const float*)d_in[7];
    const float* bv = (const float*)d_in[8];
    const float* Wo = (const float*)d_in[9];
    const float* bo = (const float*)d_in[10];
    float* out = (float*)d_out;

    cudaFuncSetAttribute((const void*)gemm_mma,
                         cudaFuncAttributeMaxDynamicSharedMemorySize, GEMM_SMEM);

    dim3 gg(DDIM/128, MM/128);   // (4, 256)

    gemm_mma<<<gg, 256, GEMM_SMEM>>>(q, 0, Wq, bq, nullptr, 1, 1);
    gemm_mma<<<gg, 256, GEMM_SMEM>>>(k, 0, Wk, bk, nullptr, 2, 1);
    gemm_mma<<<gg, 256, GEMM_SMEM>>>(v, 0, Wv, bv, nullptr, 3, 0);
    zero_kernel<<<(BB*HH*DH*DH + 255)/256, 256>>>();
    ctx_kernel<<<dim3(BB*HH, NCHUNK), 256>>>();
    apply_kernel<<<dim3(BB*HH, TT/64), 256>>>();
    gemm_mma<<<gg, 256, GEMM_SMEM>>>(nullptr, 1, Wo, bo, out, 0, 0);
}

// round 4
// speedup vs baseline: 2.4836x; 1.1025x over previous
#include <cuda_runtime.h>
#include <cuda_bf16.h>
#include <math.h>
#include <stdint.h>

// Problem constants
#define BB 4
#define TT 8192
#define DDIM 512
#define HH 8
#define DH 64
#define MM (BB*TT)     // 32768 rows
#define NCHUNK 16      // T-chunks for context reduction

// GEMM config: 128x128 CTA tile, KC=64 bf16 per chunk (128B rows), 512 threads
#define KC 64
#define NCH (DDIM/KC)            // 8
#define TILEB (128*128)          // 16384 B per tile
#define AHI 0
#define ALO TILEB
#define BHI (2*TILEB)
#define BLO (3*TILEB)
#define STAGEB (4*TILEB)         // 65536
#define GEMM_SMEM (2*STAGEB)     // 131072

// Scratch (device globals: no cudaMalloc allowed)
__device__ float g_qh[(size_t)MM*DDIM];
__device__ float g_kh[(size_t)MM*DDIM];
__device__ float g_vh[(size_t)MM*DDIM];
__device__ float g_att[(size_t)MM*DDIM];
__device__ float g_ctx[BB*HH*DH*DH];
__device__ float g_ksum[BB*HH*DH];
__device__ __nv_bfloat16 g_whi[4][DDIM*DDIM];
__device__ __nv_bfloat16 g_wlo[4][DDIM*DDIM];

// ---------------------------------------------------------------------------
// helpers
// ---------------------------------------------------------------------------
__device__ __forceinline__ uint32_t smem_u32(const void* p) {
    uint32_t a;
    asm("{ .reg .u64 t; cvta.to.shared.u64 t, %1; cvt.u32.u64 %0, t; }" : "=r"(a) : "l"(p));
    return a;
}
__device__ __forceinline__ void ldsm4(uint32_t* r, uint32_t addr) {
    asm volatile("ldmatrix.sync.aligned.m8n8.x4.shared.b16 {%0,%1,%2,%3}, [%4];"
                 : "=r"(r[0]), "=r"(r[1]), "=r"(r[2]), "=r"(r[3]) : "r"(addr));
}
__device__ __forceinline__ void mma_bf16(float* c, const uint32_t* a, const uint32_t* b) {
    asm volatile("mma.sync.aligned.m16n8k16.row.col.f32.bf16.bf16.f32 "
                 "{%0,%1,%2,%3}, {%4,%5,%6,%7}, {%8,%9}, {%0,%1,%2,%3};"
                 : "+f"(c[0]), "+f"(c[1]), "+f"(c[2]), "+f"(c[3])
                 : "r"(a[0]), "r"(a[1]), "r"(a[2]), "r"(a[3]), "r"(b[0]), "r"(b[1]));
}
__device__ __forceinline__ void cpasync16(uint32_t dst, const void* src) {
    asm volatile("cp.async.cg.shared.global [%0], [%1], 16;" :: "r"(dst), "l"(src) : "memory");
}
__device__ __forceinline__ void cp_commit() {
    asm volatile("cp.async.commit_group;" ::: "memory");
}
__device__ __forceinline__ void cp_wait0() {
    asm volatile("cp.async.wait_group 0;" ::: "memory");
}
// packs: high half = hi_f, low half = lo_f (memory order: lo first)
__device__ __forceinline__ uint32_t cvt_bf16x2(float hi_f, float lo_f) {
    uint32_t r;
    asm("cvt.rn.bf16x2.f32 %0, %1, %2;" : "=r"(r) : "f"(hi_f), "f"(lo_f));
    return r;
}
__device__ __forceinline__ void cvt_hl(float4 v, uint2& hi, uint2& lo) {
    uint32_t h01 = cvt_bf16x2(v.y, v.x);
    uint32_t h23 = cvt_bf16x2(v.w, v.z);
    float fx = __uint_as_float(h01 << 16);
    float fy = __uint_as_float(h01 & 0xFFFF0000u);
    float fz = __uint_as_float(h23 << 16);
    float fw = __uint_as_float(h23 & 0xFFFF0000u);
    hi.x = h01; hi.y = h23;
    lo.x = cvt_bf16x2(v.y - fy, v.x - fx);
    lo.y = cvt_bf16x2(v.w - fw, v.z - fz);
}

// ---------------------------------------------------------------------------
// Pre-convert all 4 weight matrices to bf16 hi/lo (once; L2-resident after)
// ---------------------------------------------------------------------------
__global__ void precvt_w(const float* __restrict__ Wq, const float* __restrict__ Wk,
                         const float* __restrict__ Wv, const float* __restrict__ Wo)
{
    const int idx = blockIdx.x * blockDim.x + threadIdx.x;   // 0..65535 per matrix (x4 floats)
    const int w = blockIdx.y;
    const float* src = (w == 0) ? Wq : (w == 1) ? Wk : (w == 2) ? Wv : Wo;
    float4 v = *(const float4*)(src + (size_t)idx * 4);
    uint2 h, l;
    cvt_hl(v, h, l);
    *(uint2*)((char*)g_whi[w] + (size_t)idx * 8) = h;
    *(uint2*)((char*)g_wlo[w] + (size_t)idx * 8) = l;
}

// ---------------------------------------------------------------------------
// GEMM: Y[m,n] = sum_k X[m,k]*W[n,k] + bias[n]  (optionally elu(x)+1)
// 128x128 CTA, 512 threads (4x4 warps, warp tile 32x32), hi/lo bf16 3-MMA.
// A: LDG fp32 -> cvt -> STS (2-chunk lookahead). B: cp.async from g_whi/g_wlo.
// ---------------------------------------------------------------------------
__global__ void __launch_bounds__(512)
gemm_mma(const float* __restrict__ Xext, int xsel, int ws,
         const float* __restrict__ bias,
         float* __restrict__ Yext, int ysel, int act)
{
    extern __shared__ char smem[];
    const float* X = (xsel == 1) ? g_att : Xext;
    float* Y = Yext;
    if      (ysel == 1) Y = g_qh;
    else if (ysel == 2) Y = g_kh;
    else if (ysel == 3) Y = g_vh;
    const __nv_bfloat16* whi = g_whi[ws];
    const __nv_bfloat16* wlo = g_wlo[ws];

    const uint32_t sb = smem_u32(smem);
    const int tid = threadIdx.x;
    const int wid = tid >> 5, lane = tid & 31;
    const int wm = wid >> 2, wn = wid & 3;       // 4 x 4 warp grid
    const int g = lane >> 2, tg = lane & 3;
    const int m0 = blockIdx.y * 128, n0 = blockIdx.x * 128;

    float acc[2][4][4];
#pragma unroll
    for (int i = 0; i < 2; i++)
#pragma unroll
        for (int j = 0; j < 4; j++)
#pragma unroll
            for (int r = 0; r < 4; r++) acc[i][j][r] = 0.f;

    float4 ra[4];

    // --- helpers as lambdas ---
    auto ldgA = [&](int k0) {
#pragma unroll
        for (int it = 0; it < 4; it++) {
            int f = it * 512 + tid;
            int r = f >> 4, cs = f & 15;
            ra[it] = *(const float4*)(X + (size_t)(m0 + r) * DDIM + k0 + cs * 4);
        }
    };
    auto stsA = [&](int stage) {
        char* base = smem + stage * STAGEB;
#pragma unroll
        for (int it = 0; it < 4; it++) {
            int f = it * 512 + tid;
            int r = f >> 4, cs = f & 15;
            int off = r * 128 + ((((cs >> 1) ^ (r & 7)) << 4) + (cs & 1) * 8);
            uint2 h, l;
            cvt_hl(ra[it], h, l);
            *(uint2*)(base + AHI + off) = h;
            *(uint2*)(base + ALO + off) = l;
        }
    };
    auto issueB = [&](int stage, int kc) {
        const uint32_t stb = sb + stage * STAGEB;
        const int k0 = kc * KC;
#pragma unroll
        for (int it = 0; it < 2; it++) {
            int f = it * 512 + tid;
            int r = f >> 3, u = f & 7;
            uint32_t sw = (uint32_t)(r * 128 + ((u ^ (r & 7)) << 4));
            const char* sh = (const char*)(whi + (size_t)(n0 + r) * DDIM + k0) + u * 16;
            const char* sl = (const char*)(wlo + (size_t)(n0 + r) * DDIM + k0) + u * 16;
            cpasync16(stb + BHI + sw, sh);
            cpasync16(stb + BLO + sw, sl);
        }
        cp_commit();
    };

    // --- prologue: chunk 0 into stage 0; chunk 1 A into regs ---
    ldgA(0);
    issueB(0, 0);
    stsA(0);
    ldgA(KC);

    for (int kc = 0; kc < NCH; kc++) {
        const int cur = kc & 1;
        cp_wait0();
        __syncthreads();

        if (kc < NCH - 1) {
            issueB(1 - cur, kc + 1);
            stsA(1 - cur);
        }
        if (kc < NCH - 2) ldgA((kc + 2) * KC);

        const uint32_t st = sb + cur * STAGEB;
#pragma unroll
        for (int ks = 0; ks < 4; ks++) {
            uint32_t ah[2][4], al[2][4];
#pragma unroll
            for (int mi = 0; mi < 2; mi++) {
                int rA = wm * 32 + mi * 16 + (lane & 15);
                int cA = ks * 2 + (lane >> 4);
                uint32_t ad = st + AHI + rA * 128 + ((cA ^ (rA & 7)) << 4);
                ldsm4(ah[mi], ad);
                ldsm4(al[mi], ad + TILEB);
            }
            uint32_t bh[4][2], bl[4][2];
#pragma unroll
            for (int np = 0; np < 2; np++) {
                int rB = wn * 32 + np * 16 + ((lane >> 4) << 3) + (lane & 7);
                int cB = ks * 2 + ((lane >> 3) & 1);
                uint32_t bd = st + BHI + rB * 128 + ((cB ^ (rB & 7)) << 4);
                uint32_t r4[4];
                ldsm4(r4, bd);
                bh[np*2][0] = r4[0]; bh[np*2][1] = r4[1];
                bh[np*2+1][0] = r4[2]; bh[np*2+1][1] = r4[3];
                ldsm4(r4, bd + TILEB);
                bl[np*2][0] = r4[0]; bl[np*2][1] = r4[1];
                bl[np*2+1][0] = r4[2]; bl[np*2+1][1] = r4[3];
            }
#pragma unroll
            for (int mi = 0; mi < 2; mi++)
#pragma unroll
                for (int ni = 0; ni < 4; ni++) {
                    mma_bf16(acc[mi][ni], ah[mi], bh[ni]);
                    mma_bf16(acc[mi][ni], ah[mi], bl[ni]);
                    mma_bf16(acc[mi][ni], al[mi], bh[ni]);
                }
        }
        __syncthreads();
    }

    // epilogue: bias + optional elu+1
#pragma unroll
    for (int mi = 0; mi < 2; mi++) {
#pragma unroll
        for (int ni = 0; ni < 4; ni++) {
            const int col = n0 + wn * 32 + ni * 8 + tg * 2;
            const float b0 = bias[col], b1 = bias[col + 1];
#pragma unroll
            for (int half = 0; half < 2; half++) {
                const int row = m0 + wm * 32 + mi * 16 + g + half * 8;
                float2 o;
                o.x = acc[mi][ni][half * 2 + 0] + b0;
                o.y = acc[mi][ni][half * 2 + 1] + b1;
                if (act) {
                    o.x = (o.x > 0.f) ? o.x + 1.f : expf(o.x);
                    o.y = (o.y > 0.f) ? o.y + 1.f : expf(o.y);
                }
                *(float2*)(Y + (size_t)row * DDIM + col) = o;
            }
        }
    }
}

// ---------------------------------------------------------------------------
// Zero accumulators
// ---------------------------------------------------------------------------
__global__ void zero_kernel()
{
    int i = blockIdx.x * blockDim.x + threadIdx.x;
    if (i < BB*HH*DH*DH) g_ctx[i]  = 0.f;
    if (i < BB*HH*DH)    g_ksum[i] = 0.f;
}

// ---------------------------------------------------------------------------
// Context reduction: ctx[b,h,c,d] = sum_t kh*vh ; ksum[b,h,c] = sum_t kh
// ---------------------------------------------------------------------------
__global__ __launch_bounds__(256)
void ctx_kernel()
{
    const int bh = blockIdx.x;
    const int chunk = blockIdx.y;
    const int b = bh >> 3, h = bh & 7;

    __shared__ float ks[32][64];
    __shared__ float vs[32][64];

    const int tid = threadIdx.x;
    const int cb = tid >> 4;
    const int db = tid & 15;

    float acc[4][4];
#pragma unroll
    for (int i = 0; i < 4; i++)
#pragma unroll
        for (int j = 0; j < 4; j++) acc[i][j] = 0.f;
    float ksacc = 0.f;

    const int tbase = b*TT + chunk * (TT/NCHUNK);

    for (int tt = 0; tt < TT/NCHUNK; tt += 32) {
#pragma unroll
        for (int qq = 0; qq < 2; qq++) {
            const int fi = qq*256 + tid;
            const int r  = fi >> 4;
            const int c4 = fi & 15;
            const size_t gofs = (size_t)(tbase + tt + r) * DDIM + h*DH + c4*4;
            *(float4*)&ks[r][c4*4] = *(const float4*)(g_kh + gofs);
            *(float4*)&vs[r][c4*4] = *(const float4*)(g_vh + gofs);
        }
        __syncthreads();

        if (tid < 64) {
#pragma unroll
            for (int t = 0; t < 32; t++) ksacc += ks[t][tid];
        }

#pragma unroll 8
        for (int t = 0; t < 32; t++) {
            float4 av = *(const float4*)&ks[t][cb*4];
            float4 bv = *(const float4*)&vs[t][db*4];
            float ar[4] = {av.x, av.y, av.z, av.w};
            float br[4] = {bv.x, bv.y, bv.z, bv.w};
#pragma unroll
            for (int i = 0; i < 4; i++)
#pragma unroll
                for (int j = 0; j < 4; j++)
                    acc[i][j] += ar[i] * br[j];
        }
        __syncthreads();
    }

    float* cp = g_ctx + bh * DH * DH;
#pragma unroll
    for (int i = 0; i < 4; i++)
#pragma unroll
        for (int j = 0; j < 4; j++)
            atomicAdd(&cp[(cb*4+i)*DH + (db*4+j)], acc[i][j]);
    if (tid < 64) atomicAdd(&g_ksum[bh*DH + tid], ksacc);
}

// ---------------------------------------------------------------------------
// Apply: g_att = (qh @ ctx) / (qh @ ksum)
// ---------------------------------------------------------------------------
__global__ __launch_bounds__(256)
void apply_kernel()
{
    const int bh = blockIdx.x;
    const int tile = blockIdx.y;
    const int b = bh >> 3, h = bh & 7;

    __shared__ float ctxs[64][68];
    __shared__ float qsm[64][68];
    __shared__ float dsm[64];

    const int tid = threadIdx.x;
    const int t0 = tile * 64;
    const float* cp = g_ctx + bh * 4096;

#pragma unroll
    for (int qq = 0; qq < 4; qq++) {
        const int fi = qq*256 + tid;
        const int r  = fi >> 4;
        const int c4 = fi & 15;
        *(float4*)&ctxs[r][c4*4] = *(const float4*)(cp + r*64 + c4*4);
        const size_t gofs = (size_t)(b*TT + t0 + r) * DDIM + h*DH + c4*4;
        *(float4*)&qsm[r][c4*4] = *(const float4*)(g_qh + gofs);
    }
    __syncthreads();

    if (tid < 64) {
        const float* kp = g_ksum + bh * DH;
        float dn = 0.f;
#pragma unroll
        for (int c = 0; c < 64; c++) dn += qsm[tid][c] * kp[c];
        dsm[tid] = dn;
    }
    __syncthreads();

    const int tsub = tid >> 4;
    const int dq   = (tid & 15) * 4;
#pragma unroll
    for (int ts = 0; ts < 4; ts++) {
        const int t = ts*16 + tsub;
        float4 acc = {0.f, 0.f, 0.f, 0.f};
#pragma unroll
        for (int c = 0; c < 64; c++) {
            const float qv = qsm[t][c];
            const float4 cv = *(const float4*)&ctxs[c][dq];
            acc.x += qv * cv.x;
            acc.y += qv * cv.y;
            acc.z += qv * cv.z;
            acc.w += qv * cv.w;
        }
        const float inv = 1.f / dsm[t];
        float4 o = {acc.x*inv, acc.y*inv, acc.z*inv, acc.w*inv};
        const size_t gofs = (size_t)(b*TT + t0 + t) * DDIM + h*DH + dq;
        *(float4*)(g_att + gofs) = o;
    }
}

// ---------------------------------------------------------------------------
extern "C" void kernel_launch(void* const* d_in, const int* in_sizes, int n_in,
                              void* d_out, int out_size)
{
    const float* q  = (const float*)d_in[0];
    const float* k  = (const float*)d_in[1];
    const float* v  = (const float*)d_in[2];
    const float* Wq = (const float*)d_in[3];
    const float* bq = (const float*)d_in[4];
    const float* Wk = (const float*)d_in[5];
    const float* bk = (const float*)d_in[6];
    const float* Wv = (const float*)d_in[7];
    const float* bv = (const float*)d_in[8];
    const float* Wo = (const float*)d_in[9];
    const float* bo = (const float*)d_in[10];
    float* out = (float*)d_out;

    cudaFuncSetAttribute((const void*)gemm_mma,
                         cudaFuncAttributeMaxDynamicSharedMemorySize, GEMM_SMEM);

    dim3 gg(DDIM/128, MM/128);   // (4, 256)

    precvt_w<<<dim3(DDIM*DDIM/4/256, 4), 256>>>(Wq, Wk, Wv, Wo);
    gemm_mma<<<gg, 512, GEMM_SMEM>>>(q, 0, 0, bq, nullptr, 1, 1);
    gemm_mma<<<gg, 512, GEMM_SMEM>>>(k, 0, 1, bk, nullptr, 2, 1);
    gemm_mma<<<gg, 512, GEMM_SMEM>>>(v, 0, 2, bv, nullptr, 3, 0);
    zero_kernel<<<(BB*HH*DH*DH + 255)/256, 256>>>();
    ctx_kernel<<<dim3(BB*HH, NCHUNK), 256>>>();
    apply_kernel<<<dim3(BB*HH, TT/64), 256>>>();
    gemm_mma<<<gg, 512, GEMM_SMEM>>>(nullptr, 1, 3, bo, out, 0, 0);
}